// round 4
// baseline (speedup 1.0000x reference)
#include <cuda_runtime.h>
#include <math.h>

#define BATCH 8
#define CIN   256
#define HH    64
#define WW    64
#define HWX   (HH*WW)        // 4096
#define CO    256
#define K2    9
#define KTOT  (CIN*K2)       // 2304
#define HO    128
#define WO    128

// ---------------- scratch (__device__ globals; no allocs allowed) ----------------
__device__ __align__(16) float g_wcombT[KTOT*32];        // [kidx][o<32] offset+mask weights, transposed
__device__ __align__(16) float g_wregT [KTOT*CO];        // [kidx][o]    deform weights, transposed
__device__ __align__(16) float g_wupR  [4*1024*CO];      // [phase][ci*4+t][o] transposed-conv weights per phase
__device__ float g_bn1s[CO], g_bn1b[CO], g_bn2s[CO], g_bn2b[CO];
__device__ __align__(16) float g_offmask[BATCH*27*HWX];  // raw offset(18)+mask-logit(9) conv output
__device__ __align__(16) float g_coef[BATCH*K2*HWX*4];   // bilinear weights * mask * validity
__device__ __align__(16) int   g_sidx[BATCH*K2*HWX*4];   // clamped gather indices within a channel
__device__ __align__(16) float g_h1[BATCH*CO*HWX];       // after deform-conv + BN1 + ReLU

// ---------------- prep: BN fold ----------------
__global__ void prep_bn(const float* __restrict__ g1, const float* __restrict__ b1,
                        const float* __restrict__ m1, const float* __restrict__ v1,
                        const float* __restrict__ g2, const float* __restrict__ b2,
                        const float* __restrict__ m2, const float* __restrict__ v2) {
    int o = threadIdx.x;
    float s1 = g1[o] * rsqrtf(v1[o] + 1e-5f);
    g_bn1s[o] = s1;  g_bn1b[o] = b1[o] - m1[o]*s1;
    float s2 = g2[o] * rsqrtf(v2[o] + 1e-5f);
    g_bn2s[o] = s2;  g_bn2b[o] = b2[o] - m2[o]*s2;
}

// ---------------- prep: weight reorganization ----------------
__global__ void prep_w(const float* __restrict__ w_off, const float* __restrict__ w_mod,
                       const float* __restrict__ w_reg, const float* __restrict__ w_up) {
    int tid = blockIdx.x*blockDim.x + threadIdx.x;
    int nt  = gridDim.x*blockDim.x;
    // combined offset/mask weight matrix, transposed: [kidx][32]
    for (int i = tid; i < KTOT*32; i += nt) {
        int kidx = i >> 5, o = i & 31;
        float v = 0.f;
        if (o < 18)      v = w_off[o*KTOT + kidx];
        else if (o < 27) v = w_mod[(o-18)*KTOT + kidx];
        g_wcombT[i] = v;
    }
    // deform weights transposed: [kidx][o]
    for (int i = tid; i < KTOT*CO; i += nt) {
        int kidx = i >> 8, o = i & 255;
        g_wregT[i] = w_reg[o*KTOT + kidx];
    }
    // transposed-conv weights per output phase: [ph][ci*4 + ty*2+tx][o]
    for (int i = tid; i < 4*1024*CO; i += nt) {
        int o  = i & 255;
        int tt = (i >> 8) & 3;
        int ci = (i >> 10) & 255;
        int ph = i >> 18;
        int fy = ph >> 1, fx = ph & 1;
        int ty = tt >> 1, tx = tt & 1;
        int ky = fy ? (ty ? 0 : 2) : (ty ? 3 : 1);
        int kx = fx ? (tx ? 0 : 2) : (tx ? 3 : 1);
        g_wupR[i] = w_up[((ci*CO + o)*4 + ky)*4 + kx];
    }
}

// ---------------- kernel 1: offset + mask conv (27ch, 3x3, pad 1) ----------------
// GEMM: M=32(27 used), N=64 (one image row), K=2304.  grid (64 rows, 8 batch)
__global__ void __launch_bounds__(256) k_offconv(const float* __restrict__ x,
                                                 const float* __restrict__ b_off,
                                                 const float* __restrict__ b_mod) {
    int h = blockIdx.x;
    int b = blockIdx.y;
    int t = threadIdx.x;
    __shared__ float4 sW4[16][8];    // [r][8 float4] = 32 o
    __shared__ float2 sV2[16][32];   // [r][32 float2] = 64 p
    float* sW = (float*)sW4;
    float* sV = (float*)sV2;
    int ox = t & 7, py = t >> 3;     // o group (4 each), p group (2 each)
    float acc[4][2] = {};
    const float* xb = x + (size_t)b*CIN*HWX;
    for (int t0 = 0; t0 < KTOT; t0 += 16) {
        #pragma unroll
        for (int i = 0; i < 2; i++) {
            int e = t + i*256;
            int r = e >> 5, col = e & 31;
            sW[r*32 + col] = g_wcombT[(t0+r)*32 + col];
        }
        #pragma unroll
        for (int i = 0; i < 4; i++) {
            int e = t + i*256;
            int r = e >> 6, pl = e & 63;
            int kidx = t0 + r;
            int c  = kidx / 9;
            int kk = kidx - c*9;
            int ky = kk / 3;
            int kx = kk - ky*3;
            int yy = h + ky - 1;
            int xx = pl + kx - 1;
            float v = 0.f;
            if (yy >= 0 && yy < HH && xx >= 0 && xx < WW)
                v = xb[c*HWX + yy*WW + xx];
            sV[r*64 + pl] = v;
        }
        __syncthreads();
        #pragma unroll
        for (int r = 0; r < 16; r++) {
            float4 a  = sW4[r][ox];
            float2 bv = sV2[r][py];
            acc[0][0] += a.x*bv.x; acc[0][1] += a.x*bv.y;
            acc[1][0] += a.y*bv.x; acc[1][1] += a.y*bv.y;
            acc[2][0] += a.z*bv.x; acc[2][1] += a.z*bv.y;
            acc[3][0] += a.w*bv.x; acc[3][1] += a.w*bv.y;
        }
        __syncthreads();
    }
    #pragma unroll
    for (int i = 0; i < 4; i++) {
        int o = ox*4 + i;
        if (o < 27) {
            float bias = (o < 18) ? b_off[o] : b_mod[o-18];
            #pragma unroll
            for (int j = 0; j < 2; j++) {
                int p = h*WW + py*2 + j;
                g_offmask[((size_t)b*27 + o)*HWX + p] = acc[i][j] + bias;
            }
        }
    }
}

// ---------------- kernel 1b: bilinear coefficient / index precompute ----------------
__global__ void k_coef() {
    int tid = blockIdx.x*blockDim.x + threadIdx.x;   // (b*9+k)*4096 + p
    if (tid >= BATCH*K2*HWX) return;
    int p = tid & (HWX-1);
    int k = (tid >> 12) % 9;
    int b = tid / (K2*HWX);
    const float* om = g_offmask + (size_t)b*27*HWX;
    float oyv = om[(2*k  )*HWX + p];
    float oxv = om[(2*k+1)*HWX + p];
    float z   = om[(18+k )*HWX + p];
    float m = 2.f / (1.f + expf(-z));
    int hh = p >> 6, ww = p & 63;
    float py = (float)hh - 1.f + (float)(k/3) + oyv;
    float px = (float)ww - 1.f + (float)(k%3) + oxv;
    float y0f = floorf(py), x0f = floorf(px);
    float wy1 = py - y0f,  wx1 = px - x0f;
    int y0 = (int)y0f, x0 = (int)x0f;
    #pragma unroll
    for (int j = 0; j < 4; j++) {
        int jy = j >> 1, jx = j & 1;
        int yi = y0 + jy, xi = x0 + jx;
        bool valid = (yi >= 0) && (yi < HH) && (xi >= 0) && (xi < WW);
        float wt = (jy ? wy1 : 1.f - wy1) * (jx ? wx1 : 1.f - wx1) * m;
        if (!valid) wt = 0.f;
        int yc = min(max(yi, 0), HH-1);
        int xc = min(max(xi, 0), WW-1);
        g_coef[(size_t)tid*4 + j] = wt;
        g_sidx[(size_t)tid*4 + j] = yc*WW + xc;
    }
}

// ---------------- kernel 2: deform conv GEMM + BN1 + ReLU ----------------
// per block: 64 o x 64 p, K=2304; gather B-tile on the fly.  grid (64, 4, 8)
__global__ void __launch_bounds__(256) k_deform(const float* __restrict__ x) {
    int h  = blockIdx.x;          // p tile = one image row
    int o0 = blockIdx.y * 64;
    int b  = blockIdx.z;
    int t  = threadIdx.x;
    __shared__ float4 sCoef4[K2][64];
    __shared__ int4   sIdx4 [K2][64];
    __shared__ float4 sW4[16][16];
    __shared__ float4 sV4[16][16];
    float* sV = (float*)sV4;
    int p0 = h * 64;
    for (int e = t; e < K2*64; e += 256) {
        int k = e >> 6, pl = e & 63;
        int gi = (b*K2 + k)*HWX + p0 + pl;
        sCoef4[k][pl] = ((const float4*)g_coef)[gi];
        sIdx4 [k][pl] = ((const int4*)  g_sidx)[gi];
    }
    __syncthreads();
    const float* xb = x + (size_t)b*CIN*HWX;
    float acc[4][4] = {};
    int ox = t & 15, py = t >> 4;
    for (int t0 = 0; t0 < KTOT; t0 += 16) {
        {
            int r = t >> 4, c4 = t & 15;
            sW4[r][c4] = *(const float4*)(&g_wregT[(t0+r)*CO + o0 + c4*4]);
        }
        #pragma unroll
        for (int i = 0; i < 4; i++) {
            int e = t + i*256;
            int r = e >> 6, pl = e & 63;
            int kidx = t0 + r;
            int c  = kidx / 9;
            int kk = kidx - c*9;
            float4 cf = sCoef4[kk][pl];
            int4   id = sIdx4 [kk][pl];
            const float* xc = xb + c*HWX;
            sV[r*64 + pl] = cf.x*xc[id.x] + cf.y*xc[id.y] + cf.z*xc[id.z] + cf.w*xc[id.w];
        }
        __syncthreads();
        #pragma unroll
        for (int r = 0; r < 16; r++) {
            float4 a  = sW4[r][ox];
            float4 bv = sV4[r][py];
            acc[0][0] += a.x*bv.x; acc[0][1] += a.x*bv.y; acc[0][2] += a.x*bv.z; acc[0][3] += a.x*bv.w;
            acc[1][0] += a.y*bv.x; acc[1][1] += a.y*bv.y; acc[1][2] += a.y*bv.z; acc[1][3] += a.y*bv.w;
            acc[2][0] += a.z*bv.x; acc[2][1] += a.z*bv.y; acc[2][2] += a.z*bv.z; acc[2][3] += a.z*bv.w;
            acc[3][0] += a.w*bv.x; acc[3][1] += a.w*bv.y; acc[3][2] += a.w*bv.z; acc[3][3] += a.w*bv.w;
        }
        __syncthreads();
    }
    #pragma unroll
    for (int i = 0; i < 4; i++) {
        int o = o0 + ox*4 + i;
        float s = g_bn1s[o], bb = g_bn1b[o];
        #pragma unroll
        for (int j = 0; j < 4; j++) {
            int p = p0 + py*4 + j;
            float v = acc[i][j]*s + bb;
            g_h1[((size_t)b*CO + o)*HWX + p] = v > 0.f ? v : 0.f;
        }
    }
}

// ---------------- kernel 3: transposed conv (per-phase GEMM) + BN2 + ReLU ----------------
// grid (64 spatial tiles of 8x8, 4 o-tiles, b*4+phase)
__global__ void __launch_bounds__(256) k_up(float* __restrict__ out) {
    int s  = blockIdx.x;
    int o0 = blockIdx.y * 64;
    int bz = blockIdx.z;
    int b  = bz >> 2, ph = bz & 3;
    int fy = ph >> 1, fx = ph & 1;
    int u0 = (s >> 3) * 8, v0 = (s & 7) * 8;
    int t  = threadIdx.x;
    __shared__ float4 sW4[16][16];
    __shared__ float4 sV4[16][16];
    float* sV = (float*)sV4;
    float acc[4][4] = {};
    int ox = t & 15, py = t >> 4;
    const float* h1b = g_h1 + (size_t)b*CO*HWX;
    const float* wph = g_wupR + (size_t)ph*1024*CO;
    int dy1 = fy ? 1 : -1;
    int dx1 = fx ? 1 : -1;
    for (int t0 = 0; t0 < 1024; t0 += 16) {
        {
            int r = t >> 4, c4 = t & 15;
            sW4[r][c4] = *(const float4*)(&wph[(t0+r)*CO + o0 + c4*4]);
        }
        #pragma unroll
        for (int i = 0; i < 4; i++) {
            int e = t + i*256;
            int r = e >> 6, pl = e & 63;
            int kidx = t0 + r;
            int ci = kidx >> 2;
            int tt = kidx & 3;
            int ty = tt >> 1, tx = tt & 1;
            int yi = u0 + (pl >> 3) + (ty ? dy1 : 0);
            int xi = v0 + (pl & 7)  + (tx ? dx1 : 0);
            float v = 0.f;
            if (yi >= 0 && yi < HH && xi >= 0 && xi < WW)
                v = h1b[ci*HWX + yi*WW + xi];
            sV[r*64 + pl] = v;
        }
        __syncthreads();
        #pragma unroll
        for (int r = 0; r < 16; r++) {
            float4 a  = sW4[r][ox];
            float4 bv = sV4[r][py];
            acc[0][0] += a.x*bv.x; acc[0][1] += a.x*bv.y; acc[0][2] += a.x*bv.z; acc[0][3] += a.x*bv.w;
            acc[1][0] += a.y*bv.x; acc[1][1] += a.y*bv.y; acc[1][2] += a.y*bv.z; acc[1][3] += a.y*bv.w;
            acc[2][0] += a.z*bv.x; acc[2][1] += a.z*bv.y; acc[2][2] += a.z*bv.z; acc[2][3] += a.z*bv.w;
            acc[3][0] += a.w*bv.x; acc[3][1] += a.w*bv.y; acc[3][2] += a.w*bv.z; acc[3][3] += a.w*bv.w;
        }
        __syncthreads();
    }
    #pragma unroll
    for (int i = 0; i < 4; i++) {
        int o = o0 + ox*4 + i;
        float sc = g_bn2s[o], bb = g_bn2b[o];
        #pragma unroll
        for (int j = 0; j < 4; j++) {
            int pl = py*4 + j;
            int u = u0 + (pl >> 3), v = v0 + (pl & 7);
            int Y = 2*u + fy, X = 2*v + fx;
            float val = acc[i][j]*sc + bb;
            out[(((size_t)b*CO + o)*HO + Y)*WO + X] = val > 0.f ? val : 0.f;
        }
    }
}

// ---------------- launch ----------------
extern "C" void kernel_launch(void* const* d_in, const int* in_sizes, int n_in,
                              void* d_out, int out_size) {
    const float* x      = (const float*)d_in[0];
    const float* w_off  = (const float*)d_in[1];
    const float* b_off  = (const float*)d_in[2];
    const float* w_mod  = (const float*)d_in[3];
    const float* b_mod  = (const float*)d_in[4];
    const float* w_reg  = (const float*)d_in[5];
    const float* bn1_g  = (const float*)d_in[6];
    const float* bn1_b  = (const float*)d_in[7];
    const float* bn1_m  = (const float*)d_in[8];
    const float* bn1_v  = (const float*)d_in[9];
    const float* w_up   = (const float*)d_in[10];
    const float* bn2_g  = (const float*)d_in[11];
    const float* bn2_b  = (const float*)d_in[12];
    const float* bn2_m  = (const float*)d_in[13];
    const float* bn2_v  = (const float*)d_in[14];
    float* out = (float*)d_out;

    prep_bn<<<1, 256>>>(bn1_g, bn1_b, bn1_m, bn1_v, bn2_g, bn2_b, bn2_m, bn2_v);
    prep_w<<<1024, 256>>>(w_off, w_mod, w_reg, w_up);
    k_offconv<<<dim3(64, BATCH), 256>>>(x, b_off, b_mod);
    k_coef<<<(BATCH*K2*HWX + 255)/256, 256>>>();
    k_deform<<<dim3(64, 4, BATCH), 256>>>(x);
    k_up<<<dim3(64, 4, BATCH*4), 256>>>(out);
}

// round 7
// speedup vs baseline: 1.0276x; 1.0276x over previous
#include <cuda_runtime.h>
#include <math.h>

#define BATCH 8
#define CIN   256
#define HH    64
#define WW    64
#define HWX   (HH*WW)        // 4096
#define CO    256
#define K2    9
#define KTOT  (CIN*K2)       // 2304
#define HO    128
#define WO    128

// packed f32x2 helpers (Blackwell FFMA2 path)
#define PACKDUP(d, s)   asm("mov.b64 %0, {%1, %1};" : "=l"(d) : "f"(s))
#define FMA2(acc, a, b) asm("fma.rn.f32x2 %0, %1, %2, %0;" : "+l"(acc) : "l"(a), "l"(b))
#define UNPACK2(lo, hi, v) asm("mov.b64 {%0, %1}, %2;" : "=f"(lo), "=f"(hi) : "l"(v))

// ---------------- scratch ----------------
__device__ __align__(16) float  g_wcombT[KTOT*32];       // offset+mask weights, transposed
__device__ __align__(16) float  g_wregT [KTOT*CO];       // deform weights, [kidx][o]
__device__ __align__(16) float  g_wupR  [4*1024*CO];     // transposed-conv weights per phase
__device__ float g_bn1s[CO], g_bn1b[CO], g_bn2s[CO], g_bn2b[CO];
__device__ __align__(16) float  g_offmask[BATCH*27*HWX];
__device__ __align__(16) float4 g_cw[BATCH*K2*HWX];      // (wy0*m, wy1*m, wx0, wx1) with validity zeros
__device__ __align__(16) uint2  g_ci[BATCH*K2*HWX];      // packed clamped indices (2x16b each)
__device__ __align__(16) float  g_h1[BATCH*CO*HWX];      // after deform + BN1 + ReLU

// ---------------- prep: BN fold ----------------
__global__ void prep_bn(const float* __restrict__ g1, const float* __restrict__ b1,
                        const float* __restrict__ m1, const float* __restrict__ v1,
                        const float* __restrict__ g2, const float* __restrict__ b2,
                        const float* __restrict__ m2, const float* __restrict__ v2) {
    int o = threadIdx.x;
    float s1 = g1[o] * rsqrtf(v1[o] + 1e-5f);
    g_bn1s[o] = s1;  g_bn1b[o] = b1[o] - m1[o]*s1;
    float s2 = g2[o] * rsqrtf(v2[o] + 1e-5f);
    g_bn2s[o] = s2;  g_bn2b[o] = b2[o] - m2[o]*s2;
}

// ---------------- prep: weight reorganization ----------------
__global__ void prep_w(const float* __restrict__ w_off, const float* __restrict__ w_mod,
                       const float* __restrict__ w_reg, const float* __restrict__ w_up) {
    int tid = blockIdx.x*blockDim.x + threadIdx.x;
    int nt  = gridDim.x*blockDim.x;
    for (int i = tid; i < KTOT*32; i += nt) {
        int kidx = i >> 5, o = i & 31;
        float v = 0.f;
        if (o < 18)      v = w_off[o*KTOT + kidx];
        else if (o < 27) v = w_mod[(o-18)*KTOT + kidx];
        g_wcombT[i] = v;
    }
    for (int i = tid; i < KTOT*CO; i += nt) {
        int kidx = i >> 8, o = i & 255;
        g_wregT[i] = w_reg[o*KTOT + kidx];
    }
    for (int i = tid; i < 4*1024*CO; i += nt) {
        int o  = i & 255;
        int tt = (i >> 8) & 3;
        int ci = (i >> 10) & 255;
        int ph = i >> 18;
        int fy = ph >> 1, fx = ph & 1;
        int ty = tt >> 1, tx = tt & 1;
        int ky = fy ? (ty ? 0 : 2) : (ty ? 3 : 1);
        int kx = fx ? (tx ? 0 : 2) : (tx ? 3 : 1);
        g_wupR[i] = w_up[((ci*CO + o)*4 + ky)*4 + kx];
    }
}

// ---------------- kernel 1: offset + mask conv ----------------
__global__ void __launch_bounds__(256) k_offconv(const float* __restrict__ x,
                                                 const float* __restrict__ b_off,
                                                 const float* __restrict__ b_mod) {
    int h = blockIdx.x;
    int b = blockIdx.y;
    int t = threadIdx.x;
    __shared__ float4 sW4[16][8];
    __shared__ float2 sV2[16][32];
    float* sW = (float*)sW4;
    float* sV = (float*)sV2;
    int ox = t & 7, py = t >> 3;
    float acc[4][2] = {};
    const float* xb = x + (size_t)b*CIN*HWX;
    for (int t0 = 0; t0 < KTOT; t0 += 16) {
        #pragma unroll
        for (int i = 0; i < 2; i++) {
            int e = t + i*256;
            int r = e >> 5, col = e & 31;
            sW[r*32 + col] = g_wcombT[(t0+r)*32 + col];
        }
        #pragma unroll
        for (int i = 0; i < 4; i++) {
            int e = t + i*256;
            int r = e >> 6, pl = e & 63;
            int kidx = t0 + r;
            int c  = kidx / 9;
            int kk = kidx - c*9;
            int ky = kk / 3;
            int kx = kk - ky*3;
            int yy = h + ky - 1;
            int xx = pl + kx - 1;
            float v = 0.f;
            if (yy >= 0 && yy < HH && xx >= 0 && xx < WW)
                v = xb[c*HWX + yy*WW + xx];
            sV[r*64 + pl] = v;
        }
        __syncthreads();
        #pragma unroll
        for (int r = 0; r < 16; r++) {
            float4 a  = sW4[r][ox];
            float2 bv = sV2[r][py];
            acc[0][0] += a.x*bv.x; acc[0][1] += a.x*bv.y;
            acc[1][0] += a.y*bv.x; acc[1][1] += a.y*bv.y;
            acc[2][0] += a.z*bv.x; acc[2][1] += a.z*bv.y;
            acc[3][0] += a.w*bv.x; acc[3][1] += a.w*bv.y;
        }
        __syncthreads();
    }
    #pragma unroll
    for (int i = 0; i < 4; i++) {
        int o = ox*4 + i;
        if (o < 27) {
            float bias = (o < 18) ? b_off[o] : b_mod[o-18];
            #pragma unroll
            for (int j = 0; j < 2; j++) {
                int p = h*WW + py*2 + j;
                g_offmask[((size_t)b*27 + o)*HWX + p] = acc[i][j] + bias;
            }
        }
    }
}

// ---------------- kernel 1b: separable bilinear coefficients + packed indices ----------------
__global__ void k_coef() {
    int tid = blockIdx.x*blockDim.x + threadIdx.x;
    if (tid >= BATCH*K2*HWX) return;
    int p = tid & (HWX-1);
    int k = (tid >> 12) % 9;
    int b = tid / (K2*HWX);
    const float* om = g_offmask + (size_t)b*27*HWX;
    float oyv = om[(2*k  )*HWX + p];
    float oxv = om[(2*k+1)*HWX + p];
    float z   = om[(18+k )*HWX + p];
    float m = 2.f / (1.f + expf(-z));
    int hh = p >> 6, ww = p & 63;
    float py = (float)hh - 1.f + (float)(k/3) + oyv;
    float px = (float)ww - 1.f + (float)(k%3) + oxv;
    float y0f = floorf(py), x0f = floorf(px);
    float wy1 = py - y0f,  wx1 = px - x0f;
    int y0 = (int)y0f, x0 = (int)x0f;
    int y1 = y0 + 1, x1 = x0 + 1;
    float wy0m = (y0 >= 0 && y0 < HH) ? (1.f - wy1)*m : 0.f;
    float wy1m = (y1 >= 0 && y1 < HH) ? wy1*m : 0.f;
    float wx0v = (x0 >= 0 && x0 < WW) ? (1.f - wx1) : 0.f;
    float wx1v = (x1 >= 0 && x1 < WW) ? wx1 : 0.f;
    int y0c = min(max(y0,0),HH-1), y1c = min(max(y1,0),HH-1);
    int x0c = min(max(x0,0),WW-1), x1c = min(max(x1,0),WW-1);
    float4 cw; cw.x = wy0m; cw.y = wy1m; cw.z = wx0v; cw.w = wx1v;
    g_cw[tid] = cw;
    uint2 ci;
    ci.x = (unsigned)(y0c*WW + x0c) | ((unsigned)(y0c*WW + x1c) << 16);
    ci.y = (unsigned)(y1c*WW + x0c) | ((unsigned)(y1c*WW + x1c) << 16);
    g_ci[tid] = ci;
}

// ---------------- kernel 2: deform conv GEMM (FFMA2) + BN1 + ReLU ----------------
// block tile: 128 o x 128 p, thread tile 8x8 packed along p. grid (32, 2, 8)
__global__ void __launch_bounds__(256) k_deform(const float* __restrict__ x) {
    int pt = blockIdx.x;
    int o0 = blockIdx.y * 128;
    int b  = blockIdx.z;
    int t  = threadIdx.x;
    __shared__ float4 sCW[K2][128];   // 18KB
    __shared__ uint2  sCI[K2][128];   // 9KB
    __shared__ float  sW[16*128];     // 8KB
    __shared__ float  sV[16*128];     // 8KB
    int p0 = pt * 128;
    for (int e = t; e < K2*128; e += 256) {
        int k = e >> 7, pl = e & 127;
        int gi = (b*K2 + k)*HWX + p0 + pl;
        sCW[k][pl] = g_cw[gi];
        sCI[k][pl] = g_ci[gi];
    }
    __syncthreads();
    const float* xb = x + (size_t)b*CIN*HWX;
    unsigned long long acc[8][4];
    #pragma unroll
    for (int i = 0; i < 8; i++)
        #pragma unroll
        for (int j = 0; j < 4; j++) acc[i][j] = 0ULL;
    int ox = t & 15, py = t >> 4;
    for (int t0 = 0; t0 < KTOT; t0 += 16) {
        // A tile: 16 rows x 128 o
        #pragma unroll
        for (int i = 0; i < 2; i++) {
            int e = t + i*256; int r2 = e >> 5, c = e & 31;
            ((float4*)sW)[r2*32 + c] = *(const float4*)&g_wregT[(t0+r2)*CO + o0 + c*4];
        }
        // B tile: gathered samples
        #pragma unroll
        for (int i = 0; i < 8; i++) {
            int e = t + i*256; int r = e >> 7, pl = e & 127;
            int kidx = t0 + r;
            int c = kidx / 9, kk = kidx - c*9;
            float4 cw = sCW[kk][pl];
            uint2  ci = sCI[kk][pl];
            const float* xc = xb + c*HWX;
            float v00 = xc[ci.x & 0xFFFF], v01 = xc[ci.x >> 16];
            float v10 = xc[ci.y & 0xFFFF], v11 = xc[ci.y >> 16];
            sV[r*128 + pl] = cw.x*(cw.z*v00 + cw.w*v01) + cw.y*(cw.z*v10 + cw.w*v11);
        }
        __syncthreads();
        #pragma unroll
        for (int r = 0; r < 16; r++) {
            float4 a0 = ((const float4*)sW)[r*32 + ox];        // o = o0 + ox*4 + {0..3}
            float4 a1 = ((const float4*)sW)[r*32 + 16 + ox];   // o = o0 + 64 + ox*4 + {0..3}
            ulonglong2 b0 = *(const ulonglong2*)&sV[r*128 + py*8];
            ulonglong2 b1 = *(const ulonglong2*)&sV[r*128 + py*8 + 4];
            unsigned long long ad[8];
            PACKDUP(ad[0], a0.x); PACKDUP(ad[1], a0.y);
            PACKDUP(ad[2], a0.z); PACKDUP(ad[3], a0.w);
            PACKDUP(ad[4], a1.x); PACKDUP(ad[5], a1.y);
            PACKDUP(ad[6], a1.z); PACKDUP(ad[7], a1.w);
            #pragma unroll
            for (int i = 0; i < 8; i++) {
                FMA2(acc[i][0], ad[i], b0.x);
                FMA2(acc[i][1], ad[i], b0.y);
                FMA2(acc[i][2], ad[i], b1.x);
                FMA2(acc[i][3], ad[i], b1.y);
            }
        }
        __syncthreads();
    }
    #pragma unroll
    for (int i = 0; i < 8; i++) {
        int o = o0 + (i >> 2)*64 + ox*4 + (i & 3);
        float s = g_bn1s[o], bb = g_bn1b[o];
        float* dst = &g_h1[((size_t)b*CO + o)*HWX + p0 + py*8];
        #pragma unroll
        for (int jp = 0; jp < 4; jp++) {
            float lo, hi; UNPACK2(lo, hi, acc[i][jp]);
            float v0 = lo*s + bb, v1 = hi*s + bb;
            float2 st; st.x = v0 > 0.f ? v0 : 0.f; st.y = v1 > 0.f ? v1 : 0.f;
            *(float2*)&dst[jp*2] = st;
        }
    }
}

// ---------------- kernel 3: transposed conv per-phase GEMM (FFMA2) + BN2 + ReLU ----------------
// block tile: 128 o x 128 p (8u x 16v). grid (32, 2, b*4+phase)
__global__ void __launch_bounds__(256) k_up(float* __restrict__ out) {
    int s  = blockIdx.x;
    int o0 = blockIdx.y * 128;
    int bz = blockIdx.z;
    int b  = bz >> 2, ph = bz & 3;
    int fy = ph >> 1, fx = ph & 1;
    int u0 = (s >> 2) * 8, v0 = (s & 3) * 16;
    int t  = threadIdx.x;
    __shared__ float sW[16*128];
    __shared__ float sV[16*128];
    unsigned long long acc[8][4];
    #pragma unroll
    for (int i = 0; i < 8; i++)
        #pragma unroll
        for (int j = 0; j < 4; j++) acc[i][j] = 0ULL;
    int ox = t & 15, py = t >> 4;
    const float* h1b = g_h1 + (size_t)b*CO*HWX;
    const float* wph = g_wupR + (size_t)ph*1024*CO;
    int dy1 = fy ? 1 : -1;
    int dx1 = fx ? 1 : -1;
    for (int t0 = 0; t0 < 1024; t0 += 16) {
        #pragma unroll
        for (int i = 0; i < 2; i++) {
            int e = t + i*256; int r2 = e >> 5, c = e & 31;
            ((float4*)sW)[r2*32 + c] = *(const float4*)&wph[(t0+r2)*CO + o0 + c*4];
        }
        #pragma unroll
        for (int i = 0; i < 8; i++) {
            int e = t + i*256; int r = e >> 7, pl = e & 127;
            int kidx = t0 + r;
            int ci = kidx >> 2;
            int tt = kidx & 3;
            int ty = tt >> 1, tx = tt & 1;
            int yi = u0 + (pl >> 4) + (ty ? dy1 : 0);
            int xi = v0 + (pl & 15) + (tx ? dx1 : 0);
            float v = 0.f;
            if (yi >= 0 && yi < HH && xi >= 0 && xi < WW)
                v = h1b[ci*HWX + yi*WW + xi];
            sV[r*128 + pl] = v;
        }
        __syncthreads();
        #pragma unroll
        for (int r = 0; r < 16; r++) {
            float4 a0 = ((const float4*)sW)[r*32 + ox];
            float4 a1 = ((const float4*)sW)[r*32 + 16 + ox];
            ulonglong2 b0 = *(const ulonglong2*)&sV[r*128 + py*8];
            ulonglong2 b1 = *(const ulonglong2*)&sV[r*128 + py*8 + 4];
            unsigned long long ad[8];
            PACKDUP(ad[0], a0.x); PACKDUP(ad[1], a0.y);
            PACKDUP(ad[2], a0.z); PACKDUP(ad[3], a0.w);
            PACKDUP(ad[4], a1.x); PACKDUP(ad[5], a1.y);
            PACKDUP(ad[6], a1.z); PACKDUP(ad[7], a1.w);
            #pragma unroll
            for (int i = 0; i < 8; i++) {
                FMA2(acc[i][0], ad[i], b0.x);
                FMA2(acc[i][1], ad[i], b0.y);
                FMA2(acc[i][2], ad[i], b1.x);
                FMA2(acc[i][3], ad[i], b1.y);
            }
        }
        __syncthreads();
    }
    #pragma unroll
    for (int i = 0; i < 8; i++) {
        int o = o0 + (i >> 2)*64 + ox*4 + (i & 3);
        float sc = g_bn2s[o], bb = g_bn2b[o];
        float* ob = &out[(((size_t)b*CO + o)*HO)*WO];
        #pragma unroll
        for (int jp = 0; jp < 4; jp++) {
            int pl = py*8 + jp*2;
            int u = u0 + (pl >> 4), v = v0 + (pl & 15);
            int Y = 2*u + fy, X = 2*v + fx;
            float lo, hi; UNPACK2(lo, hi, acc[i][jp]);
            float v0f = lo*sc + bb, v1f = hi*sc + bb;
            ob[Y*WO + X]     = v0f > 0.f ? v0f : 0.f;
            ob[Y*WO + X + 2] = v1f > 0.f ? v1f : 0.f;
        }
    }
}

// ---------------- launch ----------------
extern "C" void kernel_launch(void* const* d_in, const int* in_sizes, int n_in,
                              void* d_out, int out_size) {
    const float* x      = (const float*)d_in[0];
    const float* w_off  = (const float*)d_in[1];
    const float* b_off  = (const float*)d_in[2];
    const float* w_mod  = (const float*)d_in[3];
    const float* b_mod  = (const float*)d_in[4];
    const float* w_reg  = (const float*)d_in[5];
    const float* bn1_g  = (const float*)d_in[6];
    const float* bn1_b  = (const float*)d_in[7];
    const float* bn1_m  = (const float*)d_in[8];
    const float* bn1_v  = (const float*)d_in[9];
    const float* w_up   = (const float*)d_in[10];
    const float* bn2_g  = (const float*)d_in[11];
    const float* bn2_b  = (const float*)d_in[12];
    const float* bn2_m  = (const float*)d_in[13];
    const float* bn2_v  = (const float*)d_in[14];
    float* out = (float*)d_out;

    prep_bn<<<1, 256>>>(bn1_g, bn1_b, bn1_m, bn1_v, bn2_g, bn2_b, bn2_m, bn2_v);
    prep_w<<<1024, 256>>>(w_off, w_mod, w_reg, w_up);
    k_offconv<<<dim3(64, BATCH), 256>>>(x, b_off, b_mod);
    k_coef<<<(BATCH*K2*HWX + 255)/256, 256>>>();
    k_deform<<<dim3(32, 2, BATCH), 256>>>(x);
    k_up<<<dim3(32, 2, BATCH*4), 256>>>(out);
}

// round 9
// speedup vs baseline: 2.0772x; 2.0214x over previous
#include <cuda_runtime.h>
#include <cuda_bf16.h>
#include <math.h>
#include <stdint.h>

#define BATCH 8
#define CIN   256
#define HH    64
#define WW    64
#define HWX   4096
#define CO    256
#define K2    9
#define KTOT  2304
#define HO    128
#define WO    128

// ---------------- scratch ----------------
__device__ __align__(16) float    g_wcombT[KTOT*32];
__device__ __align__(16) unsigned g_wAp [CO*KTOT];     // packed bf16 hi|lo deform weights [o][kidx]
__device__ __align__(16) unsigned g_wupP[4*CO*1024];   // packed up weights [ph][o][kidx]
__device__ float g_bn1s[CO], g_bn1b[CO], g_bn2s[CO], g_bn2b[CO];
__device__ __align__(16) float  g_offmask[BATCH*27*HWX];
__device__ __align__(16) float4 g_cw[BATCH*K2*HWX];
__device__ __align__(16) uint2  g_ci[BATCH*K2*HWX];
__device__ __align__(16) unsigned g_h1p[BATCH*CO*HWX]; // h1 packed bf16 hi|lo

// ---------------- helpers ----------------
__device__ __forceinline__ unsigned packbf(float v) {
    __nv_bfloat16 h = __float2bfloat16(v);
    float r = v - __bfloat162float(h);
    __nv_bfloat16 l = __float2bfloat16(r);
    return (unsigned)__bfloat16_as_ushort(h) | ((unsigned)__bfloat16_as_ushort(l) << 16);
}
__device__ __forceinline__ uint32_t smem_u32(const void* p) {
    uint32_t a;
    asm("{ .reg .u64 t; cvta.to.shared.u64 t, %1; cvt.u32.u64 %0, t; }" : "=r"(a) : "l"(p));
    return a;
}
__device__ __forceinline__ uint32_t swz(uint32_t off) { return off ^ ((off >> 3) & 0x70); }

__device__ __forceinline__ void ldm4(uint32_t* r, uint32_t addr) {
    asm volatile("ldmatrix.sync.aligned.m8n8.x4.shared.b16 {%0,%1,%2,%3}, [%4];"
        : "=r"(r[0]), "=r"(r[1]), "=r"(r[2]), "=r"(r[3]) : "r"(addr));
}
__device__ __forceinline__ void mma_bf16(float* d, const uint32_t* a, uint32_t b0, uint32_t b1) {
    asm volatile("mma.sync.aligned.m16n8k16.row.col.f32.bf16.bf16.f32 "
        "{%0,%1,%2,%3}, {%4,%5,%6,%7}, {%8,%9}, {%0,%1,%2,%3};"
        : "+f"(d[0]), "+f"(d[1]), "+f"(d[2]), "+f"(d[3])
        : "r"(a[0]), "r"(a[1]), "r"(a[2]), "r"(a[3]), "r"(b0), "r"(b1));
}

// ---------------- prep: BN fold ----------------
__global__ void prep_bn(const float* __restrict__ g1, const float* __restrict__ b1,
                        const float* __restrict__ m1, const float* __restrict__ v1,
                        const float* __restrict__ g2, const float* __restrict__ b2,
                        const float* __restrict__ m2, const float* __restrict__ v2) {
    int o = threadIdx.x;
    float s1 = g1[o] * rsqrtf(v1[o] + 1e-5f);
    g_bn1s[o] = s1;  g_bn1b[o] = b1[o] - m1[o]*s1;
    float s2 = g2[o] * rsqrtf(v2[o] + 1e-5f);
    g_bn2s[o] = s2;  g_bn2b[o] = b2[o] - m2[o]*s2;
}

// ---------------- prep: weight reorg + bf16 split ----------------
__global__ void prep_w(const float* __restrict__ w_off, const float* __restrict__ w_mod,
                       const float* __restrict__ w_reg, const float* __restrict__ w_up) {
    int tid = blockIdx.x*blockDim.x + threadIdx.x;
    int nt  = gridDim.x*blockDim.x;
    for (int i = tid; i < KTOT*32; i += nt) {
        int kidx = i >> 5, o = i & 31;
        float v = 0.f;
        if (o < 18)      v = w_off[o*KTOT + kidx];
        else if (o < 27) v = w_mod[(o-18)*KTOT + kidx];
        g_wcombT[i] = v;
    }
    for (int i = tid; i < CO*KTOT; i += nt)
        g_wAp[i] = packbf(w_reg[i]);
    for (int i = tid; i < 4*CO*1024; i += nt) {
        int tt = i & 3;
        int ci = (i >> 2) & 255;
        int o  = (i >> 10) & 255;
        int ph = i >> 18;
        int fy = ph >> 1, fx = ph & 1;
        int ty = tt >> 1, tx = tt & 1;
        int ky = fy ? (ty ? 0 : 2) : (ty ? 3 : 1);
        int kx = fx ? (tx ? 0 : 2) : (tx ? 3 : 1);
        g_wupP[i] = packbf(w_up[((ci*CO + o)*4 + ky)*4 + kx]);
    }
}

// ---------------- kernel 1: offset + mask conv (verified) ----------------
__global__ void __launch_bounds__(256) k_offconv(const float* __restrict__ x,
                                                 const float* __restrict__ b_off,
                                                 const float* __restrict__ b_mod) {
    int h = blockIdx.x;
    int b = blockIdx.y;
    int t = threadIdx.x;
    __shared__ float4 sW4[16][8];
    __shared__ float2 sV2[16][32];
    float* sW = (float*)sW4;
    float* sV = (float*)sV2;
    int ox = t & 7, py = t >> 3;
    float acc[4][2] = {};
    const float* xb = x + (size_t)b*CIN*HWX;
    for (int t0 = 0; t0 < KTOT; t0 += 16) {
        #pragma unroll
        for (int i = 0; i < 2; i++) {
            int e = t + i*256;
            int r = e >> 5, col = e & 31;
            sW[r*32 + col] = g_wcombT[(t0+r)*32 + col];
        }
        #pragma unroll
        for (int i = 0; i < 4; i++) {
            int e = t + i*256;
            int r = e >> 6, pl = e & 63;
            int kidx = t0 + r;
            int c  = kidx / 9;
            int kk = kidx - c*9;
            int ky = kk / 3;
            int kx = kk - ky*3;
            int yy = h + ky - 1;
            int xx = pl + kx - 1;
            float v = 0.f;
            if (yy >= 0 && yy < HH && xx >= 0 && xx < WW)
                v = xb[c*HWX + yy*WW + xx];
            sV[r*64 + pl] = v;
        }
        __syncthreads();
        #pragma unroll
        for (int r = 0; r < 16; r++) {
            float4 a  = sW4[r][ox];
            float2 bv = sV2[r][py];
            acc[0][0] += a.x*bv.x; acc[0][1] += a.x*bv.y;
            acc[1][0] += a.y*bv.x; acc[1][1] += a.y*bv.y;
            acc[2][0] += a.z*bv.x; acc[2][1] += a.z*bv.y;
            acc[3][0] += a.w*bv.x; acc[3][1] += a.w*bv.y;
        }
        __syncthreads();
    }
    #pragma unroll
    for (int i = 0; i < 4; i++) {
        int o = ox*4 + i;
        if (o < 27) {
            float bias = (o < 18) ? b_off[o] : b_mod[o-18];
            #pragma unroll
            for (int j = 0; j < 2; j++) {
                int p = h*WW + py*2 + j;
                g_offmask[((size_t)b*27 + o)*HWX + p] = acc[i][j] + bias;
            }
        }
    }
}

// ---------------- kernel 1b: bilinear coefficients (verified) ----------------
__global__ void k_coef() {
    int tid = blockIdx.x*blockDim.x + threadIdx.x;
    if (tid >= BATCH*K2*HWX) return;
    int p = tid & (HWX-1);
    int k = (tid >> 12) % 9;
    int b = tid / (K2*HWX);
    const float* om = g_offmask + (size_t)b*27*HWX;
    float oyv = om[(2*k  )*HWX + p];
    float oxv = om[(2*k+1)*HWX + p];
    float z   = om[(18+k )*HWX + p];
    float m = 2.f / (1.f + expf(-z));
    int hh = p >> 6, ww = p & 63;
    float py = (float)hh - 1.f + (float)(k/3) + oyv;
    float px = (float)ww - 1.f + (float)(k%3) + oxv;
    float y0f = floorf(py), x0f = floorf(px);
    float wy1 = py - y0f,  wx1 = px - x0f;
    int y0 = (int)y0f, x0 = (int)x0f;
    int y1 = y0 + 1, x1 = x0 + 1;
    float wy0m = (y0 >= 0 && y0 < HH) ? (1.f - wy1)*m : 0.f;
    float wy1m = (y1 >= 0 && y1 < HH) ? wy1*m : 0.f;
    float wx0v = (x0 >= 0 && x0 < WW) ? (1.f - wx1) : 0.f;
    float wx1v = (x1 >= 0 && x1 < WW) ? wx1 : 0.f;
    int y0c = min(max(y0,0),HH-1), y1c = min(max(y1,0),HH-1);
    int x0c = min(max(x0,0),WW-1), x1c = min(max(x1,0),WW-1);
    float4 cw; cw.x = wy0m; cw.y = wy1m; cw.z = wx0v; cw.w = wx1v;
    g_cw[tid] = cw;
    uint2 ci;
    ci.x = (unsigned)(y0c*WW + x0c) | ((unsigned)(y0c*WW + x1c) << 16);
    ci.y = (unsigned)(y1c*WW + x0c) | ((unsigned)(y1c*WW + x1c) << 16);
    g_ci[tid] = ci;
}

// ================= GEMM tile geometry (both big kernels) =================
// CTA 512 thr = 16 warps (4m x 4n); block M=256(o) x N=128(p); warp 64x32; KC=64.
// smem tiles: rows x 64 k bf16, 128B rows, SW128 swizzle.
#define AH_OFF 0
#define AL_OFF 32768
#define BH_OFF 65536
#define BL_OFF 81920
#define GD_END 98304
#define D_CW   98304
#define D_CI   (98304 + 18432)
#define D_SMEM (98304 + 18432 + 9216 + 1024)
#define U_SMEM (98304 + 1024)

// ---------------- kernel 2: deform conv GEMM (HMMA bf16 3-term) ----------------
__global__ void __launch_bounds__(512) k_deform(const float* __restrict__ x) {
    extern __shared__ __align__(16) char smem[];
    uint32_t sraw = smem_u32(smem);
    uint32_t s0 = (sraw + 1023) & ~1023u;
    char* Bp = smem + (s0 - sraw);
    const int p0 = blockIdx.x * 128;
    const int b  = blockIdx.y;
    const int t  = threadIdx.x;
    const int w  = t >> 5, lane = t & 31;
    const int m0 = (w >> 2) * 64, n0 = (w & 3) * 32;

    float4* sCW = (float4*)(Bp + D_CW);
    uint2*  sCI = (uint2*) (Bp + D_CI);
    for (int e = t; e < K2*128; e += 512) {
        int kk = e >> 7, pl = e & 127;
        int gi = (b*K2 + kk)*HWX + p0 + pl;
        sCW[e] = g_cw[gi];
        sCI[e] = g_ci[gi];
    }
    __syncthreads();

    const float* xb = x + (size_t)b*CIN*HWX;
    float acc[4][4][4] = {};
    const int fpl = t & 127;          // fill: p row
    const int fkq = t >> 7;           // fill: k quarter (0..3)

    for (int ch = 0; ch < 36; ch++) {
        int t0 = ch * 64;
        // ---- B fill: gathered bilinear samples, [p][k] hi/lo ----
        #pragma unroll
        for (int kp = 0; kp < 8; kp++) {
            int kpi = fkq*8 + kp;              // k-pair in chunk (0..31)
            float v[2];
            #pragma unroll
            for (int s2 = 0; s2 < 2; s2++) {
                int kidx = t0 + kpi*2 + s2;
                int c = kidx / 9;
                int kk = kidx - c*9;
                float4 cw = sCW[kk*128 + fpl];
                uint2  ci = sCI[kk*128 + fpl];
                const float* xc = xb + c*HWX;
                v[s2] = cw.x*(cw.z*xc[ci.x & 0xFFFF] + cw.w*xc[ci.x >> 16])
                      + cw.y*(cw.z*xc[ci.y & 0xFFFF] + cw.w*xc[ci.y >> 16]);
            }
            unsigned pw0 = packbf(v[0]), pw1 = packbf(v[1]);
            unsigned hw = __byte_perm(pw0, pw1, 0x5410);
            unsigned lw = __byte_perm(pw0, pw1, 0x7632);
            unsigned off = swz((unsigned)(fpl*128 + kpi*4));
            *(unsigned*)(Bp + BH_OFF + off) = hw;
            *(unsigned*)(Bp + BL_OFF + off) = lw;
        }
        // ---- A fill: weights [o][k] hi/lo ----
        #pragma unroll
        for (int i = 0; i < 16; i++) {
            int e = t + i*512;
            int orow = e >> 5, kp = e & 31;
            uint2 w2 = *(const uint2*)&g_wAp[orow*KTOT + t0 + kp*2];
            unsigned hw = __byte_perm(w2.x, w2.y, 0x5410);
            unsigned lw = __byte_perm(w2.x, w2.y, 0x7632);
            unsigned off = swz((unsigned)(orow*128 + kp*4));
            *(unsigned*)(Bp + AH_OFF + off) = hw;
            *(unsigned*)(Bp + AL_OFF + off) = lw;
        }
        __syncthreads();
        // ---- MMA ----
        const int lrow = lane & 15;
        const int lkb  = (lane >> 4) * 16;     // k-half byte offset
        #pragma unroll
        for (int ks = 0; ks < 4; ks++) {
            int kb = ks*32 + lkb;
            uint32_t bh[2][4], bl[2][4];
            #pragma unroll
            for (int nn16 = 0; nn16 < 2; nn16++) {
                uint32_t roff = (uint32_t)((n0 + nn16*16 + lrow)*128 + kb);
                ldm4(bh[nn16], s0 + BH_OFF + swz(roff));
                ldm4(bl[nn16], s0 + BL_OFF + swz(roff));
            }
            #pragma unroll
            for (int mm = 0; mm < 4; mm++) {
                uint32_t aoff = (uint32_t)((m0 + mm*16 + lrow)*128 + kb);
                uint32_t ah[4], al[4];
                ldm4(ah, s0 + AH_OFF + swz(aoff));
                ldm4(al, s0 + AL_OFF + swz(aoff));
                #pragma unroll
                for (int nn = 0; nn < 4; nn++) {
                    uint32_t b0h = bh[nn>>1][nn&1], b1h = bh[nn>>1][2+(nn&1)];
                    uint32_t b0l = bl[nn>>1][nn&1], b1l = bl[nn>>1][2+(nn&1)];
                    mma_bf16(acc[mm][nn], ah, b0h, b1h);
                    mma_bf16(acc[mm][nn], al, b0h, b1h);
                    mma_bf16(acc[mm][nn], ah, b0l, b1l);
                }
            }
        }
        __syncthreads();
    }
    // ---- epilogue: BN1 + ReLU + pack ----
    #pragma unroll
    for (int mm = 0; mm < 4; mm++) {
        #pragma unroll
        for (int nn = 0; nn < 4; nn++) {
            int c0 = n0 + nn*8 + 2*(lane & 3);
            #pragma unroll
            for (int rh = 0; rh < 2; rh++) {
                int o = m0 + mm*16 + (lane >> 2) + rh*8;
                float s = g_bn1s[o], bb = g_bn1b[o];
                float v0 = acc[mm][nn][rh*2]   * s + bb;
                float v1 = acc[mm][nn][rh*2+1] * s + bb;
                v0 = v0 > 0.f ? v0 : 0.f;
                v1 = v1 > 0.f ? v1 : 0.f;
                uint2 st; st.x = packbf(v0); st.y = packbf(v1);
                *(uint2*)&g_h1p[(((size_t)b*CO + o) << 12) + p0 + c0] = st;
            }
        }
    }
}

// ---------------- kernel 3: transposed conv GEMM (HMMA bf16 3-term) ----------------
__global__ void __launch_bounds__(512) k_up(float* __restrict__ out) {
    extern __shared__ __align__(16) char smem[];
    uint32_t sraw = smem_u32(smem);
    uint32_t s0 = (sraw + 1023) & ~1023u;
    char* Bp = smem + (s0 - sraw);
    const int bx = blockIdx.x;
    const int bz = blockIdx.y;
    const int b = bz >> 2, ph = bz & 3;
    const int fy = ph >> 1, fx = ph & 1;
    const int u0 = (bx >> 2) * 8, v0 = (bx & 3) * 16;
    const int dy1 = fy ? 1 : -1, dx1 = fx ? 1 : -1;
    const int t = threadIdx.x;
    const int w = t >> 5, lane = t & 31;
    const int m0 = (w >> 2) * 64, n0 = (w & 3) * 32;

    const unsigned* h1b = g_h1p + (((size_t)b*CO) << 12);
    const unsigned* wb  = g_wupP + ((size_t)(ph*CO) << 10);

    float acc[4][4][4] = {};
    const int fpl = t & 127;
    const int fkq = t >> 7;
    const int fuu = u0 + (fpl >> 4), fvv = v0 + (fpl & 15);

    for (int ch = 0; ch < 16; ch++) {
        int t0 = ch * 64;
        // ---- B fill: h1 taps [p][k] hi/lo ----
        #pragma unroll
        for (int kp = 0; kp < 8; kp++) {
            int kpi = fkq*8 + kp;
            int kidx0 = t0 + kpi*2;
            int ci = kidx0 >> 2;
            const unsigned* hp = h1b + ((size_t)ci << 12);
            unsigned pv[2];
            #pragma unroll
            for (int s2 = 0; s2 < 2; s2++) {
                int tt = (kidx0 + s2) & 3;
                int ty = tt >> 1, tx = tt & 1;
                int yi = fuu + (ty ? dy1 : 0);
                int xi = fvv + (tx ? dx1 : 0);
                pv[s2] = (yi >= 0 && yi < HH && xi >= 0 && xi < WW) ? hp[yi*WW + xi] : 0u;
            }
            unsigned hw = __byte_perm(pv[0], pv[1], 0x5410);
            unsigned lw = __byte_perm(pv[0], pv[1], 0x7632);
            unsigned off = swz((unsigned)(fpl*128 + kpi*4));
            *(unsigned*)(Bp + BH_OFF + off) = hw;
            *(unsigned*)(Bp + BL_OFF + off) = lw;
        }
        // ---- A fill: up weights ----
        #pragma unroll
        for (int i = 0; i < 16; i++) {
            int e = t + i*512;
            int orow = e >> 5, kp = e & 31;
            uint2 w2 = *(const uint2*)&wb[(orow << 10) + t0 + kp*2];
            unsigned hw = __byte_perm(w2.x, w2.y, 0x5410);
            unsigned lw = __byte_perm(w2.x, w2.y, 0x7632);
            unsigned off = swz((unsigned)(orow*128 + kp*4));
            *(unsigned*)(Bp + AH_OFF + off) = hw;
            *(unsigned*)(Bp + AL_OFF + off) = lw;
        }
        __syncthreads();
        const int lrow = lane & 15;
        const int lkb  = (lane >> 4) * 16;
        #pragma unroll
        for (int ks = 0; ks < 4; ks++) {
            int kb = ks*32 + lkb;
            uint32_t bh[2][4], bl[2][4];
            #pragma unroll
            for (int nn16 = 0; nn16 < 2; nn16++) {
                uint32_t roff = (uint32_t)((n0 + nn16*16 + lrow)*128 + kb);
                ldm4(bh[nn16], s0 + BH_OFF + swz(roff));
                ldm4(bl[nn16], s0 + BL_OFF + swz(roff));
            }
            #pragma unroll
            for (int mm = 0; mm < 4; mm++) {
                uint32_t aoff = (uint32_t)((m0 + mm*16 + lrow)*128 + kb);
                uint32_t ah[4], al[4];
                ldm4(ah, s0 + AH_OFF + swz(aoff));
                ldm4(al, s0 + AL_OFF + swz(aoff));
                #pragma unroll
                for (int nn = 0; nn < 4; nn++) {
                    uint32_t b0h = bh[nn>>1][nn&1], b1h = bh[nn>>1][2+(nn&1)];
                    uint32_t b0l = bl[nn>>1][nn&1], b1l = bl[nn>>1][2+(nn&1)];
                    mma_bf16(acc[mm][nn], ah, b0h, b1h);
                    mma_bf16(acc[mm][nn], al, b0h, b1h);
                    mma_bf16(acc[mm][nn], ah, b0l, b1l);
                }
            }
        }
        __syncthreads();
    }
    // ---- epilogue: BN2 + ReLU, scatter to strided output ----
    #pragma unroll
    for (int mm = 0; mm < 4; mm++) {
        #pragma unroll
        for (int nn = 0; nn < 4; nn++) {
            int c0 = n0 + nn*8 + 2*(lane & 3);
            int u = c0 >> 4, v = c0 & 15;
            int Y = 2*(u0 + u) + fy;
            int X = 2*(v0 + v) + fx;
            #pragma unroll
            for (int rh = 0; rh < 2; rh++) {
                int o = m0 + mm*16 + (lane >> 2) + rh*8;
                float s = g_bn2s[o], bb = g_bn2b[o];
                float v0f = acc[mm][nn][rh*2]   * s + bb;
                float v1f = acc[mm][nn][rh*2+1] * s + bb;
                float* ob = &out[(((size_t)b*CO + o)*HO + Y)*WO + X];
                ob[0] = v0f > 0.f ? v0f : 0.f;
                ob[2] = v1f > 0.f ? v1f : 0.f;
            }
        }
    }
}

// ---------------- launch ----------------
extern "C" void kernel_launch(void* const* d_in, const int* in_sizes, int n_in,
                              void* d_out, int out_size) {
    const float* x      = (const float*)d_in[0];
    const float* w_off  = (const float*)d_in[1];
    const float* b_off  = (const float*)d_in[2];
    const float* w_mod  = (const float*)d_in[3];
    const float* b_mod  = (const float*)d_in[4];
    const float* w_reg  = (const float*)d_in[5];
    const float* bn1_g  = (const float*)d_in[6];
    const float* bn1_b  = (const float*)d_in[7];
    const float* bn1_m  = (const float*)d_in[8];
    const float* bn1_v  = (const float*)d_in[9];
    const float* w_up   = (const float*)d_in[10];
    const float* bn2_g  = (const float*)d_in[11];
    const float* bn2_b  = (const float*)d_in[12];
    const float* bn2_m  = (const float*)d_in[13];
    const float* bn2_v  = (const float*)d_in[14];
    float* out = (float*)d_out;

    cudaFuncSetAttribute(k_deform, cudaFuncAttributeMaxDynamicSharedMemorySize, D_SMEM);
    cudaFuncSetAttribute(k_up,     cudaFuncAttributeMaxDynamicSharedMemorySize, U_SMEM);

    prep_bn<<<1, 256>>>(bn1_g, bn1_b, bn1_m, bn1_v, bn2_g, bn2_b, bn2_m, bn2_v);
    prep_w<<<1024, 256>>>(w_off, w_mod, w_reg, w_up);
    k_offconv<<<dim3(64, BATCH), 256>>>(x, b_off, b_mod);
    k_coef<<<(BATCH*K2*HWX + 255)/256, 256>>>();
    k_deform<<<dim3(32, BATCH), 512, D_SMEM>>>(x);
    k_up<<<dim3(32, BATCH*4), 512, U_SMEM>>>(out);
}

// round 10
// speedup vs baseline: 2.4488x; 1.1789x over previous
#include <cuda_runtime.h>
#include <cuda_bf16.h>
#include <math.h>
#include <stdint.h>

#define BATCH 8
#define CIN   256
#define HH    64
#define WW    64
#define HWX   4096
#define CO    256
#define K2    9
#define KTOT  2304
#define HO    128
#define WO    128

// ---------------- scratch ----------------
__device__ __align__(16) float    g_wcombT[KTOT*32];
__device__ __align__(16) unsigned g_wAh[CO*KTOT/2];    // deform weights hi plane, 2 bf16/elem [o][k/2]
__device__ __align__(16) unsigned g_wAl[CO*KTOT/2];    // lo plane
__device__ __align__(16) unsigned g_wupH[4*CO*512];    // up weights hi plane [ph][o][k/2]
__device__ __align__(16) unsigned g_wupL[4*CO*512];    // lo plane
__device__ float g_bn1s[CO], g_bn1b[CO], g_bn2s[CO], g_bn2b[CO];
__device__ __align__(16) float  g_offmask[BATCH*27*HWX];
__device__ __align__(16) float4 g_cw[BATCH*K2*HWX];
__device__ __align__(16) uint2  g_ci[BATCH*K2*HWX];
__device__ __align__(16) unsigned g_h1p[BATCH*CO*HWX]; // h1 packed bf16 hi|lo

// ---------------- helpers ----------------
__device__ __forceinline__ unsigned packbf(float v) {
    __nv_bfloat16 h = __float2bfloat16(v);
    float r = v - __bfloat162float(h);
    __nv_bfloat16 l = __float2bfloat16(r);
    return (unsigned)__bfloat16_as_ushort(h) | ((unsigned)__bfloat16_as_ushort(l) << 16);
}
__device__ __forceinline__ uint32_t smem_u32(const void* p) {
    uint32_t a;
    asm("{ .reg .u64 t; cvta.to.shared.u64 t, %1; cvt.u32.u64 %0, t; }" : "=r"(a) : "l"(p));
    return a;
}
__device__ __forceinline__ uint32_t swz(uint32_t off) { return off ^ ((off >> 3) & 0x70); }

__device__ __forceinline__ void ldm4(uint32_t* r, uint32_t addr) {
    asm volatile("ldmatrix.sync.aligned.m8n8.x4.shared.b16 {%0,%1,%2,%3}, [%4];"
        : "=r"(r[0]), "=r"(r[1]), "=r"(r[2]), "=r"(r[3]) : "r"(addr));
}
__device__ __forceinline__ void mma_bf16(float* d, const uint32_t* a, uint32_t b0, uint32_t b1) {
    asm volatile("mma.sync.aligned.m16n8k16.row.col.f32.bf16.bf16.f32 "
        "{%0,%1,%2,%3}, {%4,%5,%6,%7}, {%8,%9}, {%0,%1,%2,%3};"
        : "+f"(d[0]), "+f"(d[1]), "+f"(d[2]), "+f"(d[3])
        : "r"(a[0]), "r"(a[1]), "r"(a[2]), "r"(a[3]), "r"(b0), "r"(b1));
}
__device__ __forceinline__ void cpa16(uint32_t dst, const void* src) {
    asm volatile("cp.async.cg.shared.global [%0], [%1], 16;" :: "r"(dst), "l"(src));
}
#define CPA_COMMIT() asm volatile("cp.async.commit_group;" ::: "memory")
#define CPA_WAIT0()  asm volatile("cp.async.wait_group 0;" ::: "memory")

// ---------------- prep: BN fold ----------------
__global__ void prep_bn(const float* __restrict__ g1, const float* __restrict__ b1,
                        const float* __restrict__ m1, const float* __restrict__ v1,
                        const float* __restrict__ g2, const float* __restrict__ b2,
                        const float* __restrict__ m2, const float* __restrict__ v2) {
    int o = threadIdx.x;
    float s1 = g1[o] * rsqrtf(v1[o] + 1e-5f);
    g_bn1s[o] = s1;  g_bn1b[o] = b1[o] - m1[o]*s1;
    float s2 = g2[o] * rsqrtf(v2[o] + 1e-5f);
    g_bn2s[o] = s2;  g_bn2b[o] = b2[o] - m2[o]*s2;
}

// ---------------- prep: weight reorg + bf16 hi/lo plane split ----------------
__global__ void prep_w(const float* __restrict__ w_off, const float* __restrict__ w_mod,
                       const float* __restrict__ w_reg, const float* __restrict__ w_up) {
    int tid = blockIdx.x*blockDim.x + threadIdx.x;
    int nt  = gridDim.x*blockDim.x;
    for (int i = tid; i < KTOT*32; i += nt) {
        int kidx = i >> 5, o = i & 31;
        float v = 0.f;
        if (o < 18)      v = w_off[o*KTOT + kidx];
        else if (o < 27) v = w_mod[(o-18)*KTOT + kidx];
        g_wcombT[i] = v;
    }
    // deform weight planes: pair k values
    for (int i = tid; i < CO*KTOT/2; i += nt) {
        unsigned p0 = packbf(w_reg[2*i]);
        unsigned p1 = packbf(w_reg[2*i+1]);
        g_wAh[i] = __byte_perm(p0, p1, 0x5410);
        g_wAl[i] = __byte_perm(p0, p1, 0x7632);
    }
    // up weight planes: [ph][o][kidx'=ci*4+tt], pair kidx'
    for (int i = tid; i < 4*CO*512; i += nt) {
        int pr = i & 511;                 // k-pair index
        int o  = (i >> 9) & 255;
        int ph = i >> 17;
        int fy = ph >> 1, fx = ph & 1;
        unsigned pp[2];
        #pragma unroll
        for (int s2 = 0; s2 < 2; s2++) {
            int kidx = pr*2 + s2;
            int ci = kidx >> 2, tt = kidx & 3;
            int ty = tt >> 1, tx = tt & 1;
            int ky = fy ? (ty ? 0 : 2) : (ty ? 3 : 1);
            int kx = fx ? (tx ? 0 : 2) : (tx ? 3 : 1);
            pp[s2] = packbf(w_up[((ci*CO + o)*4 + ky)*4 + kx]);
        }
        g_wupH[i] = __byte_perm(pp[0], pp[1], 0x5410);
        g_wupL[i] = __byte_perm(pp[0], pp[1], 0x7632);
    }
}

// ---------------- kernel 1: offset + mask conv (verified) ----------------
__global__ void __launch_bounds__(256) k_offconv(const float* __restrict__ x,
                                                 const float* __restrict__ b_off,
                                                 const float* __restrict__ b_mod) {
    int h = blockIdx.x;
    int b = blockIdx.y;
    int t = threadIdx.x;
    __shared__ float4 sW4[16][8];
    __shared__ float2 sV2[16][32];
    float* sW = (float*)sW4;
    float* sV = (float*)sV2;
    int ox = t & 7, py = t >> 3;
    float acc[4][2] = {};
    const float* xb = x + (size_t)b*CIN*HWX;
    for (int t0 = 0; t0 < KTOT; t0 += 16) {
        #pragma unroll
        for (int i = 0; i < 2; i++) {
            int e = t + i*256;
            int r = e >> 5, col = e & 31;
            sW[r*32 + col] = g_wcombT[(t0+r)*32 + col];
        }
        #pragma unroll
        for (int i = 0; i < 4; i++) {
            int e = t + i*256;
            int r = e >> 6, pl = e & 63;
            int kidx = t0 + r;
            int c  = kidx / 9;
            int kk = kidx - c*9;
            int ky = kk / 3;
            int kx = kk - ky*3;
            int yy = h + ky - 1;
            int xx = pl + kx - 1;
            float v = 0.f;
            if (yy >= 0 && yy < HH && xx >= 0 && xx < WW)
                v = xb[c*HWX + yy*WW + xx];
            sV[r*64 + pl] = v;
        }
        __syncthreads();
        #pragma unroll
        for (int r = 0; r < 16; r++) {
            float4 a  = sW4[r][ox];
            float2 bv = sV2[r][py];
            acc[0][0] += a.x*bv.x; acc[0][1] += a.x*bv.y;
            acc[1][0] += a.y*bv.x; acc[1][1] += a.y*bv.y;
            acc[2][0] += a.z*bv.x; acc[2][1] += a.z*bv.y;
            acc[3][0] += a.w*bv.x; acc[3][1] += a.w*bv.y;
        }
        __syncthreads();
    }
    #pragma unroll
    for (int i = 0; i < 4; i++) {
        int o = ox*4 + i;
        if (o < 27) {
            float bias = (o < 18) ? b_off[o] : b_mod[o-18];
            #pragma unroll
            for (int j = 0; j < 2; j++) {
                int p = h*WW + py*2 + j;
                g_offmask[((size_t)b*27 + o)*HWX + p] = acc[i][j] + bias;
            }
        }
    }
}

// ---------------- kernel 1b: bilinear coefficients (verified) ----------------
__global__ void k_coef() {
    int tid = blockIdx.x*blockDim.x + threadIdx.x;
    if (tid >= BATCH*K2*HWX) return;
    int p = tid & (HWX-1);
    int k = (tid >> 12) % 9;
    int b = tid / (K2*HWX);
    const float* om = g_offmask + (size_t)b*27*HWX;
    float oyv = om[(2*k  )*HWX + p];
    float oxv = om[(2*k+1)*HWX + p];
    float z   = om[(18+k )*HWX + p];
    float m = 2.f / (1.f + expf(-z));
    int hh = p >> 6, ww = p & 63;
    float py = (float)hh - 1.f + (float)(k/3) + oyv;
    float px = (float)ww - 1.f + (float)(k%3) + oxv;
    float y0f = floorf(py), x0f = floorf(px);
    float wy1 = py - y0f,  wx1 = px - x0f;
    int y0 = (int)y0f, x0 = (int)x0f;
    int y1 = y0 + 1, x1 = x0 + 1;
    float wy0m = (y0 >= 0 && y0 < HH) ? (1.f - wy1)*m : 0.f;
    float wy1m = (y1 >= 0 && y1 < HH) ? wy1*m : 0.f;
    float wx0v = (x0 >= 0 && x0 < WW) ? (1.f - wx1) : 0.f;
    float wx1v = (x1 >= 0 && x1 < WW) ? wx1 : 0.f;
    int y0c = min(max(y0,0),HH-1), y1c = min(max(y1,0),HH-1);
    int x0c = min(max(x0,0),WW-1), x1c = min(max(x1,0),WW-1);
    float4 cw; cw.x = wy0m; cw.y = wy1m; cw.z = wx0v; cw.w = wx1v;
    g_cw[tid] = cw;
    uint2 ci;
    ci.x = (unsigned)(y0c*WW + x0c) | ((unsigned)(y0c*WW + x1c) << 16);
    ci.y = (unsigned)(y1c*WW + x0c) | ((unsigned)(y1c*WW + x1c) << 16);
    g_ci[tid] = ci;
}

// ================= GEMM tile geometry =================
// CTA 512 thr = 16 warps (4m x 4n); block M=256(o) x N=128(p); warp 64x32; KC=64.
// Double-buffered: buffer stride 96KB. Within buffer: AH 0, AL 32K, BH 64K, BL 80K.
#define BUFS   98304
#define AH_OFF 0
#define AL_OFF 32768
#define BH_OFF 65536
#define BL_OFF 81920
#define D_CW   (2*BUFS)
#define D_CI   (2*BUFS + 18432)
#define D_SMEM (2*BUFS + 18432 + 9216 + 1024)
#define U_SMEM (2*BUFS + 1024)

// ---------------- kernel 2: deform conv GEMM (HMMA, pipelined) ----------------
__global__ void __launch_bounds__(512) k_deform(const float* __restrict__ x) {
    extern __shared__ __align__(16) char smem[];
    uint32_t sraw = smem_u32(smem);
    uint32_t s0 = (sraw + 1023) & ~1023u;
    char* Bp = smem + (s0 - sraw);
    const int p0 = blockIdx.x * 128;
    const int b  = blockIdx.y;
    const int t  = threadIdx.x;
    const int w  = t >> 5, lane = t & 31;
    const int m0 = (w >> 2) * 64, n0 = (w & 3) * 32;

    float4* sCW = (float4*)(Bp + D_CW);
    uint2*  sCI = (uint2*) (Bp + D_CI);
    for (int e = t; e < K2*128; e += 512) {
        int kk = e >> 7, pl = e & 127;
        int gi = (b*K2 + kk)*HWX + p0 + pl;
        sCW[e] = g_cw[gi];
        sCI[e] = g_ci[gi];
    }
    const float* xb = x + (size_t)b*CIN*HWX;
    float acc[4][4][4] = {};
    const int fpl = t & 127;
    const int fkq = t >> 7;

    // A fill (cp.async): 8 x 16B per thread per chunk
    auto fillA = [&](int ch, int buf) {
        int t0h = ch * 32;   // chunk base in k-pairs
        char* dA = Bp + buf*BUFS;
        #pragma unroll
        for (int i = 0; i < 8; i++) {
            int e = t + i*512;
            int plane = e >> 11;
            int rem = e & 2047;
            int orow = rem >> 3, seg = rem & 7;
            const unsigned* srcb = plane ? g_wAl : g_wAh;
            const void* src = &srcb[orow*(KTOT/2) + t0h + seg*4];
            uint32_t dst = s0 + buf*BUFS + (plane ? AL_OFF : AH_OFF) + swz((unsigned)(orow*128 + seg*16));
            cpa16(dst, src);
        }
        (void)dA;
    };
    // B fill (gather + pack): 16 samples per thread per chunk
    auto fillB = [&](int ch, int buf) {
        int t0 = ch * 64;
        char* base = Bp + buf*BUFS;
        #pragma unroll
        for (int kp = 0; kp < 8; kp++) {
            int kpi = fkq*8 + kp;
            float v[2];
            #pragma unroll
            for (int s2 = 0; s2 < 2; s2++) {
                int kidx = t0 + kpi*2 + s2;
                int c = kidx / 9;
                int kk = kidx - c*9;
                float4 cw = sCW[kk*128 + fpl];
                uint2  ci = sCI[kk*128 + fpl];
                const float* xc = xb + c*HWX;
                v[s2] = cw.x*(cw.z*xc[ci.x & 0xFFFF] + cw.w*xc[ci.x >> 16])
                      + cw.y*(cw.z*xc[ci.y & 0xFFFF] + cw.w*xc[ci.y >> 16]);
            }
            unsigned pw0 = packbf(v[0]), pw1 = packbf(v[1]);
            unsigned off = swz((unsigned)(fpl*128 + kpi*4));
            *(unsigned*)(base + BH_OFF + off) = __byte_perm(pw0, pw1, 0x5410);
            *(unsigned*)(base + BL_OFF + off) = __byte_perm(pw0, pw1, 0x7632);
        }
    };
    auto mmaChunk = [&](int buf) {
        uint32_t sb = s0 + buf*BUFS;
        const int lrow = lane & 15;
        const int lkb  = (lane >> 4) * 16;
        #pragma unroll
        for (int ks = 0; ks < 4; ks++) {
            int kb = ks*32 + lkb;
            uint32_t bh[2][4], bl[2][4];
            #pragma unroll
            for (int nn16 = 0; nn16 < 2; nn16++) {
                uint32_t roff = (uint32_t)((n0 + nn16*16 + lrow)*128 + kb);
                ldm4(bh[nn16], sb + BH_OFF + swz(roff));
                ldm4(bl[nn16], sb + BL_OFF + swz(roff));
            }
            #pragma unroll
            for (int mm = 0; mm < 4; mm++) {
                uint32_t aoff = (uint32_t)((m0 + mm*16 + lrow)*128 + kb);
                uint32_t ah[4], al[4];
                ldm4(ah, sb + AH_OFF + swz(aoff));
                ldm4(al, sb + AL_OFF + swz(aoff));
                #pragma unroll
                for (int nn = 0; nn < 4; nn++) {
                    uint32_t b0h = bh[nn>>1][nn&1], b1h = bh[nn>>1][2+(nn&1)];
                    uint32_t b0l = bl[nn>>1][nn&1], b1l = bl[nn>>1][2+(nn&1)];
                    mma_bf16(acc[mm][nn], ah, b0h, b1h);
                    mma_bf16(acc[mm][nn], al, b0h, b1h);
                    mma_bf16(acc[mm][nn], ah, b0l, b1l);
                }
            }
        }
    };

    // prologue
    __syncthreads();          // coef tiles ready
    fillA(0, 0); CPA_COMMIT();
    fillB(0, 0);
    CPA_WAIT0();
    __syncthreads();
    for (int ch = 0; ch < 36; ch++) {
        int cur = ch & 1, nxt = cur ^ 1;
        if (ch < 35) { fillA(ch+1, nxt); CPA_COMMIT(); }
        mmaChunk(cur);
        if (ch < 35) { fillB(ch+1, nxt); CPA_WAIT0(); }
        __syncthreads();
    }
    // epilogue: BN1 + ReLU + pack
    #pragma unroll
    for (int mm = 0; mm < 4; mm++) {
        #pragma unroll
        for (int nn = 0; nn < 4; nn++) {
            int c0 = n0 + nn*8 + 2*(lane & 3);
            #pragma unroll
            for (int rh = 0; rh < 2; rh++) {
                int o = m0 + mm*16 + (lane >> 2) + rh*8;
                float s = g_bn1s[o], bb = g_bn1b[o];
                float v0 = acc[mm][nn][rh*2]   * s + bb;
                float v1 = acc[mm][nn][rh*2+1] * s + bb;
                v0 = v0 > 0.f ? v0 : 0.f;
                v1 = v1 > 0.f ? v1 : 0.f;
                uint2 st; st.x = packbf(v0); st.y = packbf(v1);
                *(uint2*)&g_h1p[(((size_t)b*CO + o) << 12) + p0 + c0] = st;
            }
        }
    }
}

// ---------------- kernel 3: transposed conv GEMM (HMMA, pipelined) ----------------
__global__ void __launch_bounds__(512) k_up(float* __restrict__ out) {
    extern __shared__ __align__(16) char smem[];
    uint32_t sraw = smem_u32(smem);
    uint32_t s0 = (sraw + 1023) & ~1023u;
    char* Bp = smem + (s0 - sraw);
    const int bx = blockIdx.x;
    const int bz = blockIdx.y;
    const int b = bz >> 2, ph = bz & 3;
    const int fy = ph >> 1, fx = ph & 1;
    const int u0 = (bx >> 2) * 8, v0 = (bx & 3) * 16;
    const int dy1 = fy ? 1 : -1, dx1 = fx ? 1 : -1;
    const int t = threadIdx.x;
    const int w = t >> 5, lane = t & 31;
    const int m0 = (w >> 2) * 64, n0 = (w & 3) * 32;

    const unsigned* h1b = g_h1p + (((size_t)b*CO) << 12);
    const unsigned* wbH = g_wupH + ((size_t)(ph*CO) << 9);
    const unsigned* wbL = g_wupL + ((size_t)(ph*CO) << 9);

    float acc[4][4][4] = {};
    const int fpl = t & 127;
    const int fkq = t >> 7;
    const int fuu = u0 + (fpl >> 4), fvv = v0 + (fpl & 15);

    auto fillA = [&](int ch, int buf) {
        int t0h = ch * 32;
        #pragma unroll
        for (int i = 0; i < 8; i++) {
            int e = t + i*512;
            int plane = e >> 11;
            int rem = e & 2047;
            int orow = rem >> 3, seg = rem & 7;
            const unsigned* srcb = plane ? wbL : wbH;
            const void* src = &srcb[(orow << 9) + t0h + seg*4];
            uint32_t dst = s0 + buf*BUFS + (plane ? AL_OFF : AH_OFF) + swz((unsigned)(orow*128 + seg*16));
            cpa16(dst, src);
        }
    };
    auto fillB = [&](int ch, int buf) {
        int t0 = ch * 64;
        char* base = Bp + buf*BUFS;
        #pragma unroll
        for (int kp = 0; kp < 8; kp++) {
            int kpi = fkq*8 + kp;
            int kidx0 = t0 + kpi*2;
            int ci = kidx0 >> 2;
            const unsigned* hp = h1b + ((size_t)ci << 12);
            unsigned pv[2];
            #pragma unroll
            for (int s2 = 0; s2 < 2; s2++) {
                int tt = (kidx0 + s2) & 3;
                int ty = tt >> 1, tx = tt & 1;
                int yi = fuu + (ty ? dy1 : 0);
                int xi = fvv + (tx ? dx1 : 0);
                pv[s2] = (yi >= 0 && yi < HH && xi >= 0 && xi < WW) ? hp[yi*WW + xi] : 0u;
            }
            unsigned off = swz((unsigned)(fpl*128 + kpi*4));
            *(unsigned*)(base + BH_OFF + off) = __byte_perm(pv[0], pv[1], 0x5410);
            *(unsigned*)(base + BL_OFF + off) = __byte_perm(pv[0], pv[1], 0x7632);
        }
    };
    auto mmaChunk = [&](int buf) {
        uint32_t sb = s0 + buf*BUFS;
        const int lrow = lane & 15;
        const int lkb  = (lane >> 4) * 16;
        #pragma unroll
        for (int ks = 0; ks < 4; ks++) {
            int kb = ks*32 + lkb;
            uint32_t bh[2][4], bl[2][4];
            #pragma unroll
            for (int nn16 = 0; nn16 < 2; nn16++) {
                uint32_t roff = (uint32_t)((n0 + nn16*16 + lrow)*128 + kb);
                ldm4(bh[nn16], sb + BH_OFF + swz(roff));
                ldm4(bl[nn16], sb + BL_OFF + swz(roff));
            }
            #pragma unroll
            for (int mm = 0; mm < 4; mm++) {
                uint32_t aoff = (uint32_t)((m0 + mm*16 + lrow)*128 + kb);
                uint32_t ah[4], al[4];
                ldm4(ah, sb + AH_OFF + swz(aoff));
                ldm4(al, sb + AL_OFF + swz(aoff));
                #pragma unroll
                for (int nn = 0; nn < 4; nn++) {
                    uint32_t b0h = bh[nn>>1][nn&1], b1h = bh[nn>>1][2+(nn&1)];
                    uint32_t b0l = bl[nn>>1][nn&1], b1l = bl[nn>>1][2+(nn&1)];
                    mma_bf16(acc[mm][nn], ah, b0h, b1h);
                    mma_bf16(acc[mm][nn], al, b0h, b1h);
                    mma_bf16(acc[mm][nn], ah, b0l, b1l);
                }
            }
        }
    };

    fillA(0, 0); CPA_COMMIT();
    fillB(0, 0);
    CPA_WAIT0();
    __syncthreads();
    for (int ch = 0; ch < 16; ch++) {
        int cur = ch & 1, nxt = cur ^ 1;
        if (ch < 15) { fillA(ch+1, nxt); CPA_COMMIT(); }
        mmaChunk(cur);
        if (ch < 15) { fillB(ch+1, nxt); CPA_WAIT0(); }
        __syncthreads();
    }
    // epilogue: BN2 + ReLU, strided scatter
    #pragma unroll
    for (int mm = 0; mm < 4; mm++) {
        #pragma unroll
        for (int nn = 0; nn < 4; nn++) {
            int c0 = n0 + nn*8 + 2*(lane & 3);
            int u = c0 >> 4, v = c0 & 15;
            int Y = 2*(u0 + u) + fy;
            int X = 2*(v0 + v) + fx;
            #pragma unroll
            for (int rh = 0; rh < 2; rh++) {
                int o = m0 + mm*16 + (lane >> 2) + rh*8;
                float s = g_bn2s[o], bb = g_bn2b[o];
                float v0f = acc[mm][nn][rh*2]   * s + bb;
                float v1f = acc[mm][nn][rh*2+1] * s + bb;
                float* ob = &out[(((size_t)b*CO + o)*HO + Y)*WO + X];
                ob[0] = v0f > 0.f ? v0f : 0.f;
                ob[2] = v1f > 0.f ? v1f : 0.f;
            }
        }
    }
}

// ---------------- launch ----------------
extern "C" void kernel_launch(void* const* d_in, const int* in_sizes, int n_in,
                              void* d_out, int out_size) {
    const float* x      = (const float*)d_in[0];
    const float* w_off  = (const float*)d_in[1];
    const float* b_off  = (const float*)d_in[2];
    const float* w_mod  = (const float*)d_in[3];
    const float* b_mod  = (const float*)d_in[4];
    const float* w_reg  = (const float*)d_in[5];
    const float* bn1_g  = (const float*)d_in[6];
    const float* bn1_b  = (const float*)d_in[7];
    const float* bn1_m  = (const float*)d_in[8];
    const float* bn1_v  = (const float*)d_in[9];
    const float* w_up   = (const float*)d_in[10];
    const float* bn2_g  = (const float*)d_in[11];
    const float* bn2_b  = (const float*)d_in[12];
    const float* bn2_m  = (const float*)d_in[13];
    const float* bn2_v  = (const float*)d_in[14];
    float* out = (float*)d_out;

    cudaFuncSetAttribute(k_deform, cudaFuncAttributeMaxDynamicSharedMemorySize, D_SMEM);
    cudaFuncSetAttribute(k_up,     cudaFuncAttributeMaxDynamicSharedMemorySize, U_SMEM);

    prep_bn<<<1, 256>>>(bn1_g, bn1_b, bn1_m, bn1_v, bn2_g, bn2_b, bn2_m, bn2_v);
    prep_w<<<1024, 256>>>(w_off, w_mod, w_reg, w_up);
    k_offconv<<<dim3(64, BATCH), 256>>>(x, b_off, b_mod);
    k_coef<<<(BATCH*K2*HWX + 255)/256, 256>>>();
    k_deform<<<dim3(32, BATCH), 512, D_SMEM>>>(x);
    k_up<<<dim3(32, BATCH*4), 512, U_SMEM>>>(out);
}